// round 2
// baseline (speedup 1.0000x reference)
#include <cuda_runtime.h>
#include <cstdint>

// BDToGEConverter: out[b,s,p,d] = sum_k W[p,d,k] * x[b,s,k], W fixed-sparse:
//   out[.,0,0]=Σ j·x[64+j]  out[.,0,1]=Σ j·x[96+j]
//   out[.,1,0]=Σ j·x[80+j]  out[.,1,1]=Σ j·x[112+j]       (j=0..15)
//   for all p: x10→d27 x11→d28 x12→d29 x13→d30 x14→d31 x15→d32
//              x16→d25 x17→d26 x18→d33 x19→d34
//   everything else exactly 0.
//
// Strategy: persistent blocks, build 8-row output tiles (8*1280 floats) in
// SMEM (zeroed once — nonzero slots are rewritten every batch), stream them
// out with cp.async.bulk (TMA bulk store), double-buffered.

static constexpr int BD_DIM    = 512;
static constexpr int ROW_OUT   = 1280;                 // 8*160 floats per (b,s)
static constexpr int R         = 8;                    // rows per batch (1 warp/row)
static constexpr int THREADS   = 256;                  // 8 warps
static constexpr int BUF_FLOATS = R * ROW_OUT;         // 10240
static constexpr int BUF_BYTES  = BUF_FLOATS * 4;      // 40960
static constexpr int SMEM_BYTES = 2 * BUF_BYTES;       // 81920 (double buffer)

__global__ __launch_bounds__(THREADS, 2)
void bd2ge_tma(const float* __restrict__ x, float* __restrict__ out, int n_batches)
{
    extern __shared__ float smem[];
    const int t    = threadIdx.x;
    const int warp = t >> 5;
    const int lane = t & 31;

    // zero both buffers ONCE; structurally-zero slots are never touched again
    #pragma unroll 4
    for (int i = t; i < (2 * BUF_FLOATS) / 4; i += THREADS)
        reinterpret_cast<float4*>(smem)[i] = make_float4(0.f, 0.f, 0.f, 0.f);
    __syncthreads();

    int it = 0;
    for (int bi = blockIdx.x; bi < n_batches; bi += gridDim.x, ++it) {
        float* sbuf = smem + (it & 1) * BUF_FLOATS;

        // buffer free when the bulk store issued 2 iterations ago has read it:
        // allow at most 1 outstanding group
        if (t == 0)
            asm volatile("cp.async.bulk.wait_group.read 1;" ::: "memory");
        __syncthreads();

        const long long row = (long long)bi * R + warp;
        const float*    g    = x + row * (long long)BD_DIM;
        float*          srow = sbuf + warp * ROW_OUT;

        if (lane < 16) {
            // four 16-element weighted dots, reduced via xor-shuffle (width 16)
            float m  = (float)lane;
            float a0 = g[64  + lane] * m;
            float a1 = g[80  + lane] * m;
            float a2 = g[96  + lane] * m;
            float a3 = g[112 + lane] * m;
            #pragma unroll
            for (int o = 8; o > 0; o >>= 1) {
                a0 += __shfl_xor_sync(0x0000ffffu, a0, o, 16);
                a1 += __shfl_xor_sync(0x0000ffffu, a1, o, 16);
                a2 += __shfl_xor_sync(0x0000ffffu, a2, o, 16);
                a3 += __shfl_xor_sync(0x0000ffffu, a3, o, 16);
            }
            if (lane == 0) {
                srow[0]   = a0;   // p=0, d=0
                srow[1]   = a2;   // p=0, d=1
                srow[160] = a1;   // p=1, d=0
                srow[161] = a3;   // p=1, d=1
            }
        } else if (lane < 26) {
            // opcode one-hots: x[10+l] broadcast to all 8 p-slices
            int   l = lane - 16;
            float v = g[10 + l];
            int   d = (l < 6) ? (27 + l) : (l < 8) ? (19 + l) : (25 + l);
            #pragma unroll
            for (int p = 0; p < 8; ++p)
                srow[p * 160 + d] = v;
        }
        __syncthreads();

        if (t == 0) {
            asm volatile("fence.proxy.async.shared::cta;" ::: "memory");
            unsigned saddr = (unsigned)__cvta_generic_to_shared(sbuf);
            const float* gdst = out + (long long)bi * BUF_FLOATS;
            asm volatile(
                "cp.async.bulk.global.shared::cta.bulk_group [%0], [%1], %2;"
                :: "l"(gdst), "r"(saddr), "n"(BUF_BYTES) : "memory");
            asm volatile("cp.async.bulk.commit_group;" ::: "memory");
        }
        // no trailing sync: next iteration's top sync gates buffer reuse
    }

    // drain all outstanding bulk stores before CTA exit
    if (t == 0)
        asm volatile("cp.async.bulk.wait_group 0;" ::: "memory");
}

extern "C" void kernel_launch(void* const* d_in, const int* in_sizes, int n_in,
                              void* d_out, int out_size)
{
    const float* x = (const float*)d_in[0];   // x_bd [B,S,512]
    float* out = (float*)d_out;               // [B,S,8,160]

    int n_rows    = in_sizes[0] / BD_DIM;     // B*S = 32768
    int n_batches = n_rows / R;               // 4096

    cudaFuncSetAttribute(bd2ge_tma,
                         cudaFuncAttributeMaxDynamicSharedMemorySize, SMEM_BYTES);

    int sms = 148;
    cudaDeviceGetAttribute(&sms, cudaDevAttrMultiProcessorCount, 0);
    int grid = 2 * sms;                       // persistent, 2 CTAs/SM
    if (grid > n_batches) grid = n_batches;

    bd2ge_tma<<<grid, THREADS, SMEM_BYTES>>>(x, out, n_batches);
}

// round 3
// speedup vs baseline: 1.2348x; 1.2348x over previous
#include <cuda_runtime.h>
#include <cstdint>

// BDToGEConverter: out[b,s,p,d] = sum_k W[p,d,k] * x[b,s,k], W fixed-sparse:
//   out[.,0,0]=Σ j·x[64+j]  out[.,0,1]=Σ j·x[96+j]
//   out[.,1,0]=Σ j·x[80+j]  out[.,1,1]=Σ j·x[112+j]       (j=0..15)
//   for all p: x10→d27 x11→d28 x12→d29 x13→d30 x14→d31 x15→d32
//              x16→d25 x17→d26 x18→d33 x19→d34
//   everything else exactly 0.
//
// R3: non-persistent TMA bulk-store. One CTA per 4-row tile; deep CTA
// residency provides the TMA concurrency the persistent R2 design lacked.

static constexpr int BD_DIM     = 512;
static constexpr int ROW_OUT    = 1280;               // 8*160 floats per (b,s)
static constexpr int R          = 4;                  // rows per CTA (1 warp/row)
static constexpr int THREADS    = 128;                // 4 warps
static constexpr int BUF_FLOATS = R * ROW_OUT;        // 5120
static constexpr int BUF_BYTES  = BUF_FLOATS * 4;     // 20480

__global__ __launch_bounds__(THREADS)
void bd2ge_tile(const float* __restrict__ x, float* __restrict__ out)
{
    __shared__ float sbuf[BUF_FLOATS];

    const int t    = threadIdx.x;
    const int warp = t >> 5;
    const int lane = t & 31;

    const long long row = (long long)blockIdx.x * R + warp;
    const float*    g   = x + row * (long long)BD_DIM;

    // ---- issue input loads FIRST so DRAM latency overlaps the zero-fill
    float a0 = 0.f, a1 = 0.f, a2 = 0.f, a3 = 0.f, vop = 0.f;
    int   dop = 0;
    if (lane < 16) {
        const float m = (float)lane;
        a0 = g[64  + lane] * m;
        a1 = g[80  + lane] * m;
        a2 = g[96  + lane] * m;
        a3 = g[112 + lane] * m;
    } else if (lane < 26) {
        const int l = lane - 16;
        vop = g[10 + l];
        dop = (l < 6) ? (27 + l) : (l < 8) ? (19 + l) : (25 + l);
    }

    // ---- zero the whole tile buffer (10 STS.128 per thread)
    #pragma unroll
    for (int i = t; i < BUF_FLOATS / 4; i += THREADS)
        reinterpret_cast<float4*>(sbuf)[i] = make_float4(0.f, 0.f, 0.f, 0.f);
    __syncthreads();

    // ---- write the 84 structural nonzeros for this warp's row
    float* srow = sbuf + warp * ROW_OUT;
    if (lane < 16) {
        #pragma unroll
        for (int o = 8; o > 0; o >>= 1) {
            a0 += __shfl_xor_sync(0x0000ffffu, a0, o, 16);
            a1 += __shfl_xor_sync(0x0000ffffu, a1, o, 16);
            a2 += __shfl_xor_sync(0x0000ffffu, a2, o, 16);
            a3 += __shfl_xor_sync(0x0000ffffu, a3, o, 16);
        }
        if (lane == 0) {
            srow[0]   = a0;   // p=0, d=0
            srow[1]   = a2;   // p=0, d=1
            srow[160] = a1;   // p=1, d=0
            srow[161] = a3;   // p=1, d=1
        }
    } else if (lane < 26) {
        #pragma unroll
        for (int p = 0; p < 8; ++p)
            srow[p * 160 + dop] = vop;
    }
    __syncthreads();

    // ---- one bulk store for the whole tile; wait only for the smem READ
    if (t == 0) {
        asm volatile("fence.proxy.async.shared::cta;" ::: "memory");
        unsigned saddr = (unsigned)__cvta_generic_to_shared(sbuf);
        const float* gdst = out + (long long)blockIdx.x * BUF_FLOATS;
        asm volatile(
            "cp.async.bulk.global.shared::cta.bulk_group [%0], [%1], %2;"
            :: "l"(gdst), "r"(saddr), "n"(BUF_BYTES) : "memory");
        asm volatile("cp.async.bulk.commit_group;" ::: "memory");
        asm volatile("cp.async.bulk.wait_group.read 0;" ::: "memory");
    }
}

extern "C" void kernel_launch(void* const* d_in, const int* in_sizes, int n_in,
                              void* d_out, int out_size)
{
    const float* x = (const float*)d_in[0];   // x_bd [B,S,512]
    float* out = (float*)d_out;               // [B,S,8,160]

    int n_rows = in_sizes[0] / BD_DIM;        // B*S = 32768
    int grid   = n_rows / R;                  // 8192 CTAs

    bd2ge_tile<<<grid, THREADS>>>(x, out);
}

// round 4
// speedup vs baseline: 1.5148x; 1.2267x over previous
#include <cuda_runtime.h>
#include <cstdint>

// BDToGEConverter: out[b,s,p,d] = sum_k W[p,d,k] * x[b,s,k], W fixed-sparse:
//   out[.,0,0]=Σ j·x[64+j]  out[.,0,1]=Σ j·x[96+j]
//   out[.,1,0]=Σ j·x[80+j]  out[.,1,1]=Σ j·x[112+j]       (j=0..15)
//   for all p: x10→d27 x11→d28 x12→d29 x13→d30 x14→d31 x15→d32
//              x16→d25 x17→d26 x18→d33 x19→d34 ; all else 0.
//
// R4: warp-per-row, register-composed. Each lane streams its 10 zero float4s
// with immediate-offset st.global.cs (no branches, no div/mod), then lanes
// 0..25 overwrite the 26 nonzero float4s after a __syncwarp().

static constexpr int BD_DIM   = 512;
static constexpr int ROW_OUT4 = 320;     // float4 per (b,s) row
static constexpr int THREADS  = 256;     // 8 warps = 8 rows per block

__global__ __launch_bounds__(THREADS)
void bd2ge_reg(const float* __restrict__ x, float* __restrict__ out)
{
    const unsigned FULL = 0xffffffffu;
    const int t    = threadIdx.x;
    const int warp = t >> 5;
    const int lane = t & 31;

    const long long row = (long long)blockIdx.x * 8 + warp;
    const float*    g   = x + row * (long long)BD_DIM;

    // ---- per-lane input loads (issued before the store flood)
    float a0 = 0.f, a1 = 0.f, a2 = 0.f, a3 = 0.f, vop = 0.f;
    if (lane < 16) {
        const float m = (float)lane;
        a0 = __ldg(g + 64  + lane) * m;
        a1 = __ldg(g + 80  + lane) * m;
        a2 = __ldg(g + 96  + lane) * m;
        a3 = __ldg(g + 112 + lane) * m;
    } else if (lane < 26) {
        vop = __ldg(g + 10 + (lane - 16));
    }

    // ---- flood the row with zeros: 10 immediate-offset streaming stores/lane
    float4* rowb = reinterpret_cast<float4*>(out) + row * ROW_OUT4 + lane;
    const float4 z = make_float4(0.f, 0.f, 0.f, 0.f);
    #pragma unroll
    for (int i = 0; i < 10; ++i)
        __stcs(rowb + i * 32, z);

    // ---- reductions + broadcasts (overlap with stores in flight)
    #pragma unroll
    for (int o = 8; o > 0; o >>= 1) {
        a0 += __shfl_xor_sync(FULL, a0, o, 16);
        a1 += __shfl_xor_sync(FULL, a1, o, 16);
        a2 += __shfl_xor_sync(FULL, a2, o, 16);
        a3 += __shfl_xor_sync(FULL, a3, o, 16);
    }
    float xv[10];                       // xv[j] = x[10+j], lane 16+j holds it
    #pragma unroll
    for (int j = 0; j < 10; ++j)
        xv[j] = __shfl_sync(FULL, vop, 16 + j);

    // ---- compose this lane's special float4 (26 nonzero slots per row)
    float4 sv = z;
    int    w  = 0;
    if (lane == 0)       { sv = make_float4(a0, a2, 0.f, 0.f);             w = 0; }
    else if (lane == 1)  { sv = make_float4(a1, a3, 0.f, 0.f);             w = 40; }
    else if (lane < 10)  { sv = make_float4(0.f, xv[6], xv[7], xv[0]);     w = (lane - 2) * 40 + 6; }   // d 24..27
    else if (lane < 18)  { sv = make_float4(xv[1], xv[2], xv[3], xv[4]);   w = (lane - 10) * 40 + 7; }  // d 28..31
    else if (lane < 26)  { sv = make_float4(xv[5], xv[8], xv[9], 0.f);     w = (lane - 18) * 40 + 8; }  // d 32..35

    __syncwarp();                       // order zero-flood before overwrites
    if (lane < 26)
        __stcs(reinterpret_cast<float4*>(out) + row * ROW_OUT4 + w, sv);
}

extern "C" void kernel_launch(void* const* d_in, const int* in_sizes, int n_in,
                              void* d_out, int out_size)
{
    const float* x = (const float*)d_in[0];   // x_bd [B,S,512]
    float* out = (float*)d_out;               // [B,S,8,160]

    int n_rows = in_sizes[0] / BD_DIM;        // B*S = 32768
    int grid   = n_rows / 8;                  // 4096 blocks, warp-per-row

    bd2ge_reg<<<grid, THREADS>>>(x, out);
}